// round 1
// baseline (speedup 1.0000x reference)
#include <cuda_runtime.h>
#include <math.h>

#define NELEM 16384
#define NB    16384
#define SCAN_T 1024
#define CHUNK (NB / SCAN_T)   // 16

// Scratch (allocation-free: __device__ globals)
__device__ float  g_exp[NELEM];
__device__ float  g_bsum[NB];
__device__ int    g_cnt[NB];
__device__ float  g_suf[NB];       // exclusive suffix sum of bucket sums
__device__ int    g_off[NB + 1];   // exclusive prefix sum of counts
__device__ int    g_fill[NB];
__device__ float2 g_sorted[NELEM]; // (time, exp) grouped by bucket
__device__ float  g_num;
__device__ float  g_den;

__device__ __forceinline__ int bucket_of(float t) {
    int b = (int)(t * (float)NB);
    if (b < 0) b = 0;
    if (b > NB - 1) b = NB - 1;
    return b;
}

__global__ void k0_init() {
    int i = blockIdx.x * blockDim.x + threadIdx.x;
    if (i < NB) { g_bsum[i] = 0.0f; g_cnt[i] = 0; g_fill[i] = 0; }
    if (i == 0) { g_num = 0.0f; g_den = 0.0f; }
}

__global__ void k1_bucket(const float* __restrict__ risk,
                          const float* __restrict__ time) {
    int i = blockIdx.x * blockDim.x + threadIdx.x;
    if (i >= NELEM) return;
    float e = expf(risk[i]);
    g_exp[i] = e;
    int b = bucket_of(time[i]);
    atomicAdd(&g_bsum[b], e);
    atomicAdd(&g_cnt[b], 1);
}

// Single block: exclusive prefix scan of counts -> g_off,
// exclusive suffix scan of bucket sums -> g_suf.
__global__ void k2_scan() {
    __shared__ float fpart[SCAN_T];
    __shared__ int   ipart[SCAN_T];
    int t = threadIdx.x;
    int base = t * CHUNK;

    int   cloc[CHUNK];
    float floc[CHUNK];

    int csum = 0;
#pragma unroll
    for (int k = 0; k < CHUNK; k++) { cloc[k] = csum; csum += g_cnt[base + k]; }
    float fsum = 0.0f;
#pragma unroll
    for (int k = CHUNK - 1; k >= 0; k--) { floc[k] = fsum; fsum += g_bsum[base + k]; }

    ipart[t] = csum;   // per-chunk count total
    fpart[t] = fsum;   // per-chunk float total
    __syncthreads();

    // Hillis-Steele: inclusive prefix on ipart, inclusive suffix on fpart
    for (int d = 1; d < SCAN_T; d <<= 1) {
        int   iv = ipart[t];
        int   ia = (t >= d) ? ipart[t - d] : 0;
        float fv = fpart[t];
        float fa = (t + d < SCAN_T) ? fpart[t + d] : 0.0f;
        __syncthreads();
        ipart[t] = iv + ia;
        fpart[t] = fv + fa;
        __syncthreads();
    }

    int   cbase = (t > 0) ? ipart[t - 1] : 0;            // exclusive prefix of chunk
    float fbase = (t < SCAN_T - 1) ? fpart[t + 1] : 0.0f; // exclusive suffix of chunk
#pragma unroll
    for (int k = 0; k < CHUNK; k++) {
        g_off[base + k] = cbase + cloc[k];
        g_suf[base + k] = fbase + floc[k];
    }
    if (t == 0) g_off[NB] = NELEM;
}

__global__ void k3_scatter(const float* __restrict__ time) {
    int i = blockIdx.x * blockDim.x + threadIdx.x;
    if (i >= NELEM) return;
    float t = time[i];
    int b = bucket_of(t);
    int pos = g_off[b] + atomicAdd(&g_fill[b], 1);
    g_sorted[pos] = make_float2(t, g_exp[i]);
}

__global__ void k4_loss(const float* __restrict__ risk,
                        const float* __restrict__ time,
                        const float* __restrict__ event) {
    int i = blockIdx.x * blockDim.x + threadIdx.x;
    float num = 0.0f, den = 0.0f;
    if (i < NELEM) {
        float t = time[i];
        int b = bucket_of(t);
        float s = g_suf[b];               // exact sum over strictly-higher buckets
        int k0 = g_off[b], k1 = g_off[b + 1];
        for (int k = k0; k < k1; k++) {   // exact within-bucket (handles ties, self)
            float2 p = g_sorted[k];
            if (p.x >= t) s += p.y;
        }
        float lrs = logf(s);
        float ev = event[i];
        num = ev * (risk[i] - lrs);
        den = ev;
    }
    // warp reduce
#pragma unroll
    for (int o = 16; o > 0; o >>= 1) {
        num += __shfl_down_sync(0xffffffffu, num, o);
        den += __shfl_down_sync(0xffffffffu, den, o);
    }
    __shared__ float snum[8], sden[8];
    int lane = threadIdx.x & 31, warp = threadIdx.x >> 5;
    if (lane == 0) { snum[warp] = num; sden[warp] = den; }
    __syncthreads();
    if (warp == 0) {
        num = (lane < (blockDim.x >> 5)) ? snum[lane] : 0.0f;
        den = (lane < (blockDim.x >> 5)) ? sden[lane] : 0.0f;
#pragma unroll
        for (int o = 4; o > 0; o >>= 1) {
            num += __shfl_down_sync(0xffffffffu, num, o);
            den += __shfl_down_sync(0xffffffffu, den, o);
        }
        if (lane == 0) {
            atomicAdd(&g_num, num);
            atomicAdd(&g_den, den);
        }
    }
}

__global__ void k5_final(float* __restrict__ out) {
    out[0] = -g_num / g_den;
}

extern "C" void kernel_launch(void* const* d_in, const int* in_sizes, int n_in,
                              void* d_out, int out_size) {
    const float* risk  = (const float*)d_in[0];
    const float* time  = (const float*)d_in[1];
    const float* event = (const float*)d_in[2];
    float* out = (float*)d_out;

    const int TB = 256;
    k0_init<<<(NB + TB - 1) / TB, TB>>>();
    k1_bucket<<<(NELEM + TB - 1) / TB, TB>>>(risk, time);
    k2_scan<<<1, SCAN_T>>>();
    k3_scatter<<<(NELEM + TB - 1) / TB, TB>>>(time);
    k4_loss<<<(NELEM + TB - 1) / TB, TB>>>(risk, time, event);
    k5_final<<<1, 1>>>(out);
}

// round 3
// speedup vs baseline: 2.0668x; 2.0668x over previous
#include <cuda_runtime.h>
#include <math.h>

#define NELEM 16384
#define NB    16384
#define NBLK  64
#define NTHR  256

// Scratch — __device__ globals are zero-initialized at module load; the kernel
// restores the all-zero state before exiting, so every graph replay starts
// from the same state.
__device__ float  g_bsum[NB];       // per-bucket sum of exp(risk)
__device__ int    g_head[NB];       // linked-list head per bucket; 0 = empty, else idx+1
__device__ int    g_next[NELEM];    // linked-list next (encoded, overwritten fully each run)
__device__ float2 g_te[NELEM];      // (time, exp) per element (overwritten fully each run)
__device__ float  g_suf[NB];        // exclusive suffix sum of bucket sums (overwritten)
__device__ float  g_blksum[NBLK];   // per-block chunk totals (overwritten)
__device__ float  g_num, g_den;
__device__ int    g_barcnt;         // barrier arrival counter (self-resetting)
__device__ int    g_sense;          // barrier sense flag (parity-agnostic)

// Sense-reversing grid barrier. Single counter, reused for all barriers:
// the last arriver resets the counter BEFORE flipping the sense, so waiters
// (who poll only the sense) can never observe a reset mid-wait. Works from
// any initial sense parity -> replay-safe with no end-of-kernel cleanup.
__device__ __forceinline__ void gbar() {
    __syncthreads();
    if (threadIdx.x == 0) {
        volatile int* vs = &g_sense;
        int s = *vs;
        __threadfence();
        if (atomicAdd(&g_barcnt, 1) == NBLK - 1) {
            g_barcnt = 0;
            __threadfence();
            *vs = s ^ 1;
        } else {
            while (*vs == s) { }
        }
        __threadfence();
    }
    __syncthreads();
}

__global__ void __launch_bounds__(NTHR, 1) cox_single_kernel(
    const float* __restrict__ risk,
    const float* __restrict__ time,
    const float* __restrict__ event,
    float* __restrict__ out)
{
    const int t   = threadIdx.x;
    const int blk = blockIdx.x;
    const int i   = blk * NTHR + t;   // element index == bucket-slot index

    __shared__ float s_f[NTHR];
    __shared__ float s_b[NBLK];
    __shared__ float rn[8], rd[8];

    // ---- Phase 1: exp, bucket histogram, per-bucket linked lists ----------
    const float my_risk = risk[i];
    const float my_t    = time[i];
    const float my_e    = expf(my_risk);
    int b = (int)(my_t * (float)NB);
    b = b < 0 ? 0 : (b > NB - 1 ? NB - 1 : b);

    g_te[i] = make_float2(my_t, my_e);
    atomicAdd(&g_bsum[b], my_e);
    g_next[i] = atomicExch(&g_head[b], i + 1);
    gbar();  // B1

    // ---- Phase 2a: block-local inclusive suffix scan of this chunk's bsum -
    float sumv = __ldcg(&g_bsum[i]);
    s_f[t] = sumv;
    __syncthreads();
    #pragma unroll
    for (int d = 1; d < NTHR; d <<= 1) {
        float fv = s_f[t];
        float fa = (t + d < NTHR) ? s_f[t + d] : 0.0f;
        __syncthreads();
        s_f[t] = fv + fa;
        __syncthreads();
    }
    float excl_suf = s_f[t] - sumv;          // exclusive suffix within chunk
    if (t == 0) g_blksum[blk] = s_f[0];      // chunk total
    gbar();  // B2

    // ---- Phase 2b: every block redundantly suffix-scans the 64 totals -----
    if (t < NBLK) s_b[t] = __ldcg(&g_blksum[t]);
    __syncthreads();
    #pragma unroll
    for (int d = 1; d < NBLK; d <<= 1) {
        float fv = 0.0f, fa = 0.0f;
        if (t < NBLK) { fv = s_b[t]; fa = (t + d < NBLK) ? s_b[t + d] : 0.0f; }
        __syncthreads();
        if (t < NBLK) s_b[t] = fv + fa;
        __syncthreads();
    }
    float base = (blk + 1 < NBLK) ? s_b[blk + 1] : 0.0f;  // sum over higher blocks
    g_suf[i] = base + excl_suf;              // exact sum over strictly-higher buckets
    gbar();  // B3

    // ---- Phase 3: per-element log-risk-set + loss terms -------------------
    // s = (sum over buckets > b) + exact in-bucket sum over {j : t_j >= t_i}.
    // Bucketing is monotone in t, so ties/boundaries are handled exactly here.
    float s = __ldcg(&g_suf[b]);
    int j = __ldcg(&g_head[b]);
    while (j != 0) {
        float2 p = __ldcg(&g_te[j - 1]);
        if (p.x >= my_t) s += p.y;
        j = __ldcg(&g_next[j - 1]);
    }
    float ev  = event[i];
    float num = ev * (my_risk - logf(s));
    float den = ev;

    #pragma unroll
    for (int o = 16; o > 0; o >>= 1) {
        num += __shfl_down_sync(0xffffffffu, num, o);
        den += __shfl_down_sync(0xffffffffu, den, o);
    }
    int lane = t & 31, w = t >> 5;
    if (lane == 0) { rn[w] = num; rd[w] = den; }
    __syncthreads();
    if (w == 0) {
        num = (lane < 8) ? rn[lane] : 0.0f;
        den = (lane < 8) ? rd[lane] : 0.0f;
        #pragma unroll
        for (int o = 4; o > 0; o >>= 1) {
            num += __shfl_down_sync(0xffffffffu, num, o);
            den += __shfl_down_sync(0xffffffffu, den, o);
        }
        if (lane == 0) { atomicAdd(&g_num, num); atomicAdd(&g_den, den); }
    }
    gbar();  // B4

    // ---- Phase 4: output + restore all-zero scratch state -----------------
    if (i == 0) {
        float n = __ldcg(&g_num), d = __ldcg(&g_den);
        out[0] = -n / d;
        g_num = 0.0f; g_den = 0.0f;
    }
    g_bsum[i] = 0.0f;
    g_head[i] = 0;
}

extern "C" void kernel_launch(void* const* d_in, const int* in_sizes, int n_in,
                              void* d_out, int out_size) {
    const float* risk  = (const float*)d_in[0];
    const float* time  = (const float*)d_in[1];
    const float* event = (const float*)d_in[2];
    float* out = (float*)d_out;

    cox_single_kernel<<<NBLK, NTHR>>>(risk, time, event, out);
}

// round 6
// speedup vs baseline: 2.0948x; 1.0135x over previous
#include <cuda_runtime.h>
#include <math.h>

#define NELEM 16384
#define NB    16384
#define NBLK  64
#define NTHR  256
#define CAP   16

typedef unsigned long long ull;

// Epoch-parity / epoch-tagged scratch: no cleanup pass needed.
__device__ float  g_bsum[2][NB];  // parity-double-buffered histogram (atomics)
__device__ ull    g_head[NB];     // (ep1)<<32 | (idx+1); other tag = stale/empty
__device__ float4 g_node[NELEM];  // (time, exp, next_idx_plus1_as_bits, 0) — epoch-terminated at write
__device__ float  g_chunk[NBLK];  // per-chunk totals
__device__ float2 g_bpart[NBLK];  // per-block (num, den)
__device__ ull    g_done;         // monotone; epoch = g_done >> 6
__device__ int    g_barcnt;
__device__ int    g_sense;

static __device__ __forceinline__ ull ldv64(const ull* p) {
    ull v; asm volatile("ld.global.cg.u64 %0, [%1];" : "=l"(v) : "l"(p)); return v;
}
static __device__ __forceinline__ float ldvf(const float* p) {
    float v; asm volatile("ld.global.cg.f32 %0, [%1];" : "=f"(v) : "l"(p)); return v;
}

// Grid barrier with REAL memory semantics: every thread drains its own global
// writes (threadfence) before arrival — this is the piece R5 was missing.
__device__ __forceinline__ void gbar() {
    __threadfence();
    __syncthreads();
    if (threadIdx.x == 0) {
        volatile int* vs = &g_sense;
        int s = *vs;
        if (atomicAdd(&g_barcnt, 1) == NBLK - 1) {
            g_barcnt = 0;
            __threadfence();
            *vs = s ^ 1;
        } else {
            while (*vs == s) { }
        }
        __threadfence();
    }
    __syncthreads();
}

__global__ void __launch_bounds__(NTHR, 1) cox_kernel(
    const float* __restrict__ risk,
    const float* __restrict__ time,
    const float* __restrict__ event,
    float* __restrict__ out)
{
    const int t   = threadIdx.x;
    const int blk = blockIdx.x;
    const int i   = blk * NTHR + t;

    __shared__ unsigned sh_ep1;
    __shared__ float s_f[NTHR];
    __shared__ float s_hi[2];
    __shared__ float rn[8], rd[8];

    if (t == 0) sh_ep1 = (unsigned)(ldv64(&g_done) >> 6) + 1u;
    __syncthreads();
    const unsigned ep1 = sh_ep1;
    const int par = (int)((ep1 - 1u) & 1u);

    // ---- Phase 1: exp, histogram (atomics -> L2-visible), tagged chain ----
    const float my_t = time[i];
    const float my_e = expf(risk[i]);
    int b = (int)(my_t * (float)NB);
    b = b < 0 ? 0 : (b > NB - 1 ? NB - 1 : b);

    g_bsum[par ^ 1][i] = 0.0f;                    // prep next epoch's buffer
    atomicAdd(&g_bsum[par][b], my_e);             // bulk bucket sum (robust path)
    ull disp = atomicExch(&g_head[b], ((ull)ep1 << 32) | (unsigned)(i + 1));
    unsigned nxt = ((unsigned)(disp >> 32) == ep1) ? (unsigned)(disp & 0xffffffffu) : 0u;
    g_node[i] = make_float4(my_t, my_e, __uint_as_float(nxt), 0.0f);
    gbar();  // B1

    // ---- Phase 2: this thread OWNS bucket k = i -------------------------
    const float bs = ldvf(&g_bsum[par][i]);       // histogram value, not chain

    float tarr[CAP], earr[CAP];
    int   jarr[CAP];
    int   len = 0, headj;
    {
        ull h = ldv64(&g_head[i]);
        headj = ((unsigned)(h >> 32) == ep1) ? (int)(h & 0xffffffffu) : 0;
        int j = headj;
        while (j) {                                // avg 1 node; 1 chase/node
            float4 nd = __ldcg(&g_node[j - 1]);
            if (len < CAP) { tarr[len] = nd.x; earr[len] = nd.y; jarr[len] = j - 1; }
            len++;
            j = (int)__float_as_uint(nd.z);
        }
    }

    // Block-wide inclusive suffix scan of bucket sums
    s_f[t] = bs;
    __syncthreads();
    #pragma unroll
    for (int d = 1; d < NTHR; d <<= 1) {
        float fv = s_f[t];
        float fa = (t + d < NTHR) ? s_f[t + d] : 0.0f;
        __syncthreads();
        s_f[t] = fv + fa;
        __syncthreads();
    }
    const float excl = s_f[t] - bs;               // suffix over higher buckets in chunk
    if (t == 0) g_chunk[blk] = s_f[0];            // chunk total
    gbar();  // B2 (its fences cover the g_chunk store)

    // ---- Phase 3: cross-chunk base (only own block's base needed) --------
    float hi = 0.0f;
    if (t < NBLK && t > blk) hi = ldvf(&g_chunk[t]);
    if (t < 64) {
        #pragma unroll
        for (int o = 16; o > 0; o >>= 1) hi += __shfl_down_sync(0xffffffffu, hi, o);
        if ((t & 31) == 0) s_hi[t >> 5] = hi;
    }
    __syncthreads();
    const float sb = s_hi[0] + s_hi[1] + excl;    // sum over buckets strictly > k

    // Per-element loss for every element in my bucket (exact ties in-bucket).
    float num = 0.0f, den = 0.0f;
    if (len <= CAP) {
        for (int a = 0; a < len; a++) {
            float ev = __ldg(&event[jarr[a]]);
            if (ev != 0.0f) {
                float s = sb;
                for (int m = 0; m < len; m++)
                    if (tarr[m] >= tarr[a]) s += earr[m];   // includes self
                num += ev * logf(earr[a] / s);   // = ev*(theta - log s), theta=log(exp)
                den += ev;
            }
        }
    } else {  // overflow fallback (essentially never; correctness only)
        int a = headj;
        while (a) {
            float4 na = __ldcg(&g_node[a - 1]);
            float ev = __ldg(&event[a - 1]);
            if (ev != 0.0f) {
                float s = sb;
                int m = headj;
                while (m) {
                    float4 nm = __ldcg(&g_node[m - 1]);
                    if (nm.x >= na.x) s += nm.y;
                    m = (int)__float_as_uint(nm.z);
                }
                num += ev * logf(na.y / s);
                den += ev;
            }
            a = (int)__float_as_uint(na.z);
        }
    }

    // ---- Block reduce -> ticket finalize ---------------------------------
    #pragma unroll
    for (int o = 16; o > 0; o >>= 1) {
        num += __shfl_down_sync(0xffffffffu, num, o);
        den += __shfl_down_sync(0xffffffffu, den, o);
    }
    int lane = t & 31, w = t >> 5;
    if (lane == 0) { rn[w] = num; rd[w] = den; }
    __syncthreads();
    if (t == 0) {
        float n = 0.0f, d = 0.0f;
        #pragma unroll
        for (int k = 0; k < 8; k++) { n += rn[k]; d += rd[k]; }
        g_bpart[blk] = make_float2(n, d);
        __threadfence();
        ull old = atomicAdd(&g_done, 1ULL);
        if (old == ((ull)ep1 << 6) - 1ULL) {      // last arriver of this launch
            __threadfence();
            float tn = 0.0f, td = 0.0f;
            #pragma unroll 8
            for (int c = 0; c < NBLK; c++) {
                float2 p = __ldcg(&g_bpart[c]);
                tn += p.x; td += p.y;
            }
            out[0] = -tn / td;
        }
    }
}

extern "C" void kernel_launch(void* const* d_in, const int* in_sizes, int n_in,
                              void* d_out, int out_size) {
    const float* risk  = (const float*)d_in[0];
    const float* time  = (const float*)d_in[1];
    const float* event = (const float*)d_in[2];
    float* out = (float*)d_out;
    cox_kernel<<<NBLK, NTHR>>>(risk, time, event, out);
}